// round 10
// baseline (speedup 1.0000x reference)
#include <cuda_runtime.h>
#include <cstdint>
#include <cstddef>

#define T_TOTAL 524288
#define NCHUNK  8192          // 64-row chunks
#define K1_BLK  4096          // k1: 128 rows (2 tiles) per CTA
#define TILE_R  64
#define SUPER   128           // chunks per super-chunk in k2
#define NSUPER  (NCHUNK / SUPER)
#define SEGC    32            // chunks per segment (4 segments per super)

// packed per-row gate params: {a0,a1,b0,b1} for channel pair ci -> 268MB
__device__ __align__(16) float4 g_ab[(size_t)T_TOTAL * 32];
// per-chunk aggregates and chunk-start states
__device__ __align__(16) float g_Ac[NCHUNK * 64];
__device__ __align__(16) float g_Bc[NCHUNK * 64];
__device__ __align__(16) float g_U [NCHUNK * 64];
__device__ __align__(16) float g_A2[NSUPER * 64];
__device__ __align__(16) float g_B2[NSUPER * 64];
__device__ __align__(16) float g_U2[NSUPER * 64];

typedef unsigned long long u64;

__device__ __forceinline__ u64 pk2(float lo, float hi) {
    u64 r; asm("mov.b64 %0, {%1,%2};" : "=l"(r) : "f"(lo), "f"(hi)); return r;
}
__device__ __forceinline__ float2 upk(u64 v) {
    float2 r; asm("mov.b64 {%0,%1}, %2;" : "=f"(r.x), "=f"(r.y) : "l"(v)); return r;
}
__device__ __forceinline__ void ffma2(u64 &d, u64 a, u64 b) {
    asm("fma.rn.f32x2 %0, %1, %2, %0;" : "+l"(d) : "l"(a), "l"(b));
}
__device__ __forceinline__ float sigf(float x) {
    float e = __expf(-x);
    return __fdividef(1.0f, 1.0f + e);
}

// ============================================================================
// k1: GEMM1 + gate -> g_ab (packed) + per-64-row-chunk aggregates
// Channel-pair-packed FFMA2: weights load as natural u64 pairs (no dup MOVs),
// x pre-duplicated in smem (broadcast LDS.128 reads).
// xdup layout: u64 slot(k, r) = k*64 + (r ^ (4*((k>>2)&15)))
// ============================================================================
__global__ __launch_bounds__(256, 3)
void k1_gemm1(const float* __restrict__ inp,
              const float* __restrict__ W1,
              const float* __restrict__ B1) {
    extern __shared__ float sm[];
    float4* W1i4  = (float4*)sm;                 // [0,32768): {l0,l1,r0,r1} per (k,ci)
    u64*    xd    = (u64*)(sm + 8192);           // [32768,65536): duplicated x
    float2* parts = (float2*)(sm + 16384);       // [65536,69632)

    const int tid = threadIdx.x, c = blockIdx.x;
    const int ri = tid >> 5, ci = tid & 31;

    // W1 interleaved: W1i4[k*32+ci] = {W1[k][2ci],W1[k][2ci+1],W1[k][64+2ci],W1[k][64+2ci+1]}
    #pragma unroll
    for (int p = 0; p < 8; p++) {
        int idx = tid + p * 256;
        int k = idx >> 5, cc = idx & 31;
        float2 l = *(const float2*)(W1 + k * 128 + 2 * cc);
        float2 r = *(const float2*)(W1 + k * 128 + 64 + 2 * cc);
        W1i4[idx] = make_float4(l.x, l.y, r.x, r.y);
    }
    const float bl0 = B1[2 * ci],      bl1 = B1[2 * ci + 1];
    const float br0 = B1[64 + 2 * ci], br1 = B1[64 + 2 * ci + 1];
    __syncthreads();

    #pragma unroll 1
    for (int tt = 0; tt < 2; tt++) {
        const int chunk = 2 * c + tt;
        const int t0 = chunk * TILE_R;

        // fill xdup: each thread 4 float4 loads, dup-stores STS.64 (4-way conflict)
        #pragma unroll
        for (int p = 0; p < 4; p++) {
            int i = tid + p * 256;
            int r = i >> 4, cc = i & 15;
            float4 v = *(const float4*)(inp + (size_t)(t0 + r) * 64 + 4 * cc);
            int rs = r ^ (4 * cc);              // swizzle: 4*((k>>2)&15) = 4*cc for k=4cc+j
            xd[(4 * cc + 0) * 64 + rs] = pk2(v.x, v.x);
            xd[(4 * cc + 1) * 64 + rs] = pk2(v.y, v.y);
            xd[(4 * cc + 2) * 64 + rs] = pk2(v.z, v.z);
            xd[(4 * cc + 3) * 64 + rs] = pk2(v.w, v.w);
        }
        __syncthreads();

        // GEMM1: rows 8ri..8ri+7, channel-pair accumulators accL/accR[row]
        u64 accL[8], accR[8];
        #pragma unroll
        for (int m = 0; m < 8; m++) { accL[m] = 0ull; accR[m] = 0ull; }

        #pragma unroll 1
        for (int k0 = 0; k0 < 64; k0 += 16) {
            #pragma unroll
            for (int j = 0; j < 16; j++) {
                const int k = k0 + j;
                const int s4 = 4 * ((k >> 2) & 15);
                const int b  = (8 * ri) ^ s4;
                const u64* xb = xd + k * 64;
                ulonglong2 x01 = *(const ulonglong2*)(xb + b);            // rows 8ri+0,1
                ulonglong2 x23 = *(const ulonglong2*)(xb + b + 2);        // rows 8ri+2,3
                ulonglong2 x45 = *(const ulonglong2*)(xb + (b ^ 4));      // rows 8ri+4,5
                ulonglong2 x67 = *(const ulonglong2*)(xb + (b ^ 4) + 2);  // rows 8ri+6,7
                ulonglong2 w = *(const ulonglong2*)(W1i4 + k * 32 + ci);  // .x={l0,l1} .y={r0,r1}
                ffma2(accL[0], x01.x, w.x); ffma2(accR[0], x01.x, w.y);
                ffma2(accL[1], x01.y, w.x); ffma2(accR[1], x01.y, w.y);
                ffma2(accL[2], x23.x, w.x); ffma2(accR[2], x23.x, w.y);
                ffma2(accL[3], x23.y, w.x); ffma2(accR[3], x23.y, w.y);
                ffma2(accL[4], x45.x, w.x); ffma2(accR[4], x45.x, w.y);
                ffma2(accL[5], x45.y, w.x); ffma2(accR[5], x45.y, w.y);
                ffma2(accL[6], x67.x, w.x); ffma2(accR[6], x67.x, w.y);
                ffma2(accL[7], x67.y, w.x); ffma2(accR[7], x67.y, w.y);
            }
        }

        // epilogue: sigmoid/gate per row (time order), store + compose partial
        float A0 = 1.f, B0 = 0.f, A1 = 1.f, B1v = 0.f;
        #pragma unroll
        for (int m = 0; m < 8; m++) {
            float2 hL = upk(accL[m]);
            float2 hR = upk(accR[m]);
            float l0 = sigf(hL.x + bl0);
            float l1 = sigf(hL.y + bl1);
            float r0 = sigf(hR.x + br0);
            float r1 = sigf(hR.y + br1);
            float a0 = l0 * r0, b0 = 1.f - l0;
            float a1 = l1 * r1, b1 = 1.f - l1;
            g_ab[(size_t)(t0 + 8 * ri + m) * 32 + ci] = make_float4(a0, a1, b0, b1);
            B0  = fmaf(a0, B0, b0);  A0 *= a0;
            B1v = fmaf(a1, B1v, b1); A1 *= a1;
        }
        ((float4*)parts)[ri * 32 + ci] = make_float4(A0, B0, A1, B1v);
        __syncthreads();

        if (tid < 64) {
            float Ac = 1.f, Bc = 0.f;
            #pragma unroll
            for (int g = 0; g < 8; g++) {
                float2 pp = parts[g * 64 + tid];
                Bc = fmaf(pp.x, Bc, pp.y);
                Ac *= pp.x;
            }
            g_Ac[chunk * 64 + tid] = Ac;
            g_Bc[chunk * 64 + tid] = Bc;
        }
        __syncthreads();
    }
}

// ============================================================================
// k2a: super aggregates — 4 segments x 64 channels per CTA, prefetched
// ============================================================================
__global__ __launch_bounds__(256, 8)
void k2a_super_agg() {
    __shared__ float2 parts[4 * 64];
    const int s = blockIdx.x;
    const int j = threadIdx.x & 63, seg = threadIdx.x >> 6;
    const int base = s * SUPER + seg * SEGC;

    float A = 1.f, B = 0.f;
    #pragma unroll 1
    for (int bq = 0; bq < SEGC / 8; bq++) {
        float a_[8], b_[8];
        #pragma unroll
        for (int i = 0; i < 8; i++) {
            a_[i] = g_Ac[(base + bq * 8 + i) * 64 + j];
            b_[i] = g_Bc[(base + bq * 8 + i) * 64 + j];
        }
        #pragma unroll
        for (int i = 0; i < 8; i++) { B = fmaf(a_[i], B, b_[i]); A *= a_[i]; }
    }
    parts[seg * 64 + j] = make_float2(A, B);
    __syncthreads();

    if (threadIdx.x < 64) {
        float As = 1.f, Bs = 0.f;
        #pragma unroll
        for (int g = 0; g < 4; g++) {
            float2 pp = parts[g * 64 + threadIdx.x];
            Bs = fmaf(pp.x, Bs, pp.y);
            As *= pp.x;
        }
        g_A2[s * 64 + threadIdx.x] = As;
        g_B2[s * 64 + threadIdx.x] = Bs;
    }
}

// ============================================================================
// k2b: scan over 64 supers, prefetched in batches of 16
// ============================================================================
__global__ void k2b_super_scan() {
    const int j = threadIdx.x;
    float u = 0.f;
    #pragma unroll 1
    for (int bq = 0; bq < NSUPER / 16; bq++) {
        float A_[16], B_[16];
        #pragma unroll
        for (int i = 0; i < 16; i++) {
            A_[i] = g_A2[(bq * 16 + i) * 64 + j];
            B_[i] = g_B2[(bq * 16 + i) * 64 + j];
        }
        #pragma unroll
        for (int i = 0; i < 16; i++) {
            g_U2[(bq * 16 + i) * 64 + j] = u;
            u = fmaf(A_[i], u, B_[i]);
        }
    }
}

// ============================================================================
// k2c: expand to chunk-start states — segmented + prefetched
// ============================================================================
__global__ __launch_bounds__(256, 8)
void k2c_expand() {
    __shared__ float2 parts[4 * 64];
    __shared__ float  segu [4 * 64];
    const int s = blockIdx.x;
    const int j = threadIdx.x & 63, seg = threadIdx.x >> 6;
    const int base = s * SUPER + seg * SEGC;

    float A = 1.f, B = 0.f;
    #pragma unroll 1
    for (int bq = 0; bq < SEGC / 8; bq++) {
        float a_[8], b_[8];
        #pragma unroll
        for (int i = 0; i < 8; i++) {
            a_[i] = g_Ac[(base + bq * 8 + i) * 64 + j];
            b_[i] = g_Bc[(base + bq * 8 + i) * 64 + j];
        }
        #pragma unroll
        for (int i = 0; i < 8; i++) { B = fmaf(a_[i], B, b_[i]); A *= a_[i]; }
    }
    parts[seg * 64 + j] = make_float2(A, B);
    __syncthreads();

    if (threadIdx.x < 64) {
        float u = g_U2[s * 64 + threadIdx.x];
        #pragma unroll
        for (int g = 0; g < 4; g++) {
            segu[g * 64 + threadIdx.x] = u;
            float2 pp = parts[g * 64 + threadIdx.x];
            u = fmaf(pp.x, u, pp.y);
        }
    }
    __syncthreads();

    float u = segu[seg * 64 + j];
    #pragma unroll 1
    for (int bq = 0; bq < SEGC / 8; bq++) {
        float a_[8], b_[8];
        #pragma unroll
        for (int i = 0; i < 8; i++) {
            a_[i] = g_Ac[(base + bq * 8 + i) * 64 + j];
            b_[i] = g_Bc[(base + bq * 8 + i) * 64 + j];
        }
        #pragma unroll
        for (int i = 0; i < 8; i++) {
            g_U[(base + bq * 8 + i) * 64 + j] = u;
            u = fmaf(a_[i], u, b_[i]);
        }
    }
}

// ============================================================================
// k3: load a,b -> parallel replay -> swizzled z tile -> GEMM2 -> out
// ============================================================================
__global__ __launch_bounds__(256, 4)
void k3_replay_gemm2(const float* __restrict__ W2,
                     const float* __restrict__ B2,
                     float* __restrict__ out) {
    extern __shared__ float sm[];
    float*  zsf   = sm;                          // [0,16384)
    float2* parts = (float2*)(sm + 4096);        // [16384,20480)
    float*  ust   = sm + 5120;                   // [20480,22528)
    u64*    W2d   = (u64*)(sm + 5632);           // [22528,38912)

    const int tid = threadIdx.x, c = blockIdx.x;
    const int ri = tid >> 5, ci = tid & 31;
    const int oc = tid & 31, rp = tid >> 5;
    const int t0 = c * TILE_R;

    #pragma unroll
    for (int p = 0; p < 8; p++) {
        int idx = tid + p * 256;
        float w = W2[idx];
        W2d[idx] = pk2(w, w);
    }
    const float b2 = B2[oc];
    if (c == 0 && tid < 32) out[tid] = B2[tid];

    float4 ab[8];
    #pragma unroll
    for (int e = 0; e < 8; e++)
        ab[e] = g_ab[(size_t)(t0 + 8 * ri + e) * 32 + ci];

    float A0 = 1.f, B0 = 0.f, A1 = 1.f, B1v = 0.f;
    #pragma unroll
    for (int e = 0; e < 8; e++) {
        B0  = fmaf(ab[e].x, B0,  ab[e].z);  A0 *= ab[e].x;
        B1v = fmaf(ab[e].y, B1v, ab[e].w);  A1 *= ab[e].y;
    }
    ((float4*)parts)[ri * 32 + ci] = make_float4(A0, B0, A1, B1v);
    __syncthreads();

    if (tid < 64) {
        float u = g_U[c * 64 + tid];
        #pragma unroll
        for (int g = 0; g < 8; g++) {
            ust[g * 64 + tid] = u;
            float2 pp = parts[g * 64 + tid];
            u = fmaf(pp.x, u, pp.y);
        }
    }
    __syncthreads();

    {
        float2 us = *(const float2*)(ust + ri * 64 + 2 * ci);
        float u0 = us.x, u1 = us.y;
        const int j0 = 2 * ci, j1 = 2 * ci + 1;
        #pragma unroll
        for (int e = 0; e < 8; e++) {
            u0 = fmaf(ab[e].x, u0, ab[e].z);
            u1 = fmaf(ab[e].y, u1, ab[e].w);
            int r = 8 * ri + e;
            zsf[(j0 * 16 + ((r >> 2) ^ (j0 & 15))) * 4 + (r & 3)] = u0;
            zsf[(j1 * 16 + ((r >> 2) ^ (j1 & 15))) * 4 + (r & 3)] = u1;
        }
    }
    __syncthreads();

    u64 acc0 = pk2(b2, b2), acc1 = acc0, acc2 = acc0, acc3 = acc0;
    {
        const int rb0 = 2 * rp, rb1 = 2 * rp + 1;
        const float4* zs4 = (const float4*)zsf;
        #pragma unroll 1
        for (int k0 = 0; k0 < 64; k0 += 16) {
            #pragma unroll
            for (int j = 0; j < 16; j++) {
                const int k = k0 + j;
                ulonglong2 zA = *(const ulonglong2*)(zs4 + k * 16 + (rb0 ^ j));
                ulonglong2 zB = *(const ulonglong2*)(zs4 + k * 16 + (rb1 ^ j));
                u64 wd = W2d[k * 32 + oc];
                ffma2(acc0, zA.x, wd); ffma2(acc1, zA.y, wd);
                ffma2(acc2, zB.x, wd); ffma2(acc3, zB.y, wd);
            }
        }
    }
    #pragma unroll
    for (int q = 0; q < 4; q++) {
        u64 a = (q == 0) ? acc0 : (q == 1) ? acc1 : (q == 2) ? acc2 : acc3;
        float2 v = upk(a);
        int t = t0 + 1 + 8 * rp + 2 * q;
        if (t < T_TOTAL)     out[(size_t)t * 32 + oc]       = v.x;
        if (t + 1 < T_TOTAL) out[(size_t)(t + 1) * 32 + oc] = v.y;
    }
}

// ============================================================================
// launch
// ============================================================================
extern "C" void kernel_launch(void* const* d_in, const int* in_sizes, int n_in,
                              void* d_out, int out_size) {
    const float* inp = (const float*)d_in[0];
    const float* W1  = (const float*)d_in[1];
    const float* B1  = (const float*)d_in[2];
    const float* W2  = (const float*)d_in[3];
    const float* B2  = (const float*)d_in[4];
    float* out = (float*)d_out;

    const int smem1 = 69632;
    const int smem3 = 38912;
    cudaFuncSetAttribute(k1_gemm1,        cudaFuncAttributeMaxDynamicSharedMemorySize, smem1);
    cudaFuncSetAttribute(k3_replay_gemm2, cudaFuncAttributeMaxDynamicSharedMemorySize, smem3);

    k1_gemm1<<<K1_BLK, 256, smem1>>>(inp, W1, B1);
    k2a_super_agg<<<NSUPER, 256>>>();
    k2b_super_scan<<<1, 64>>>();
    k2c_expand<<<NSUPER, 256>>>();
    k3_replay_gemm2<<<NCHUNK, 256, smem3>>>(W2, B2, out);
    (void)in_sizes; (void)n_in; (void)out_size;
}

// round 12
// speedup vs baseline: 1.1714x; 1.1714x over previous
#include <cuda_runtime.h>
#include <cuda_fp16.h>
#include <cstdint>
#include <cstddef>

#define T_TOTAL 524288
#define NCHUNK  8192          // 64-row chunks
#define K1_BLK  4096          // k1: 128 rows (2 tiles) per CTA
#define TILE_R  64
#define SUPER   128           // chunks per super-chunk in k2
#define NSUPER  (NCHUNK / SUPER)
#define SEGC    32            // chunks per segment (4 segments per super)

// packed per-row gate params, fp16: {f16x2(a0,a1), f16x2(b0,b1)} -> 134MB
__device__ __align__(16) uint2 g_ab[(size_t)T_TOTAL * 32];
// per-chunk aggregates and chunk-start states (fp32 exact path)
__device__ __align__(16) float g_Ac[NCHUNK * 64];
__device__ __align__(16) float g_Bc[NCHUNK * 64];
__device__ __align__(16) float g_U [NCHUNK * 64];
__device__ __align__(16) float g_A2[NSUPER * 64];
__device__ __align__(16) float g_B2[NSUPER * 64];
__device__ __align__(16) float g_U2[NSUPER * 64];

typedef unsigned long long u64;

__device__ __forceinline__ u64 pk2(float lo, float hi) {
    u64 r; asm("mov.b64 %0, {%1,%2};" : "=l"(r) : "f"(lo), "f"(hi)); return r;
}
__device__ __forceinline__ float2 upk(u64 v) {
    float2 r; asm("mov.b64 {%0,%1}, %2;" : "=f"(r.x), "=f"(r.y) : "l"(v)); return r;
}
__device__ __forceinline__ void ffma2(u64 &d, u64 a, u64 b) {
    asm("fma.rn.f32x2 %0, %1, %2, %0;" : "+l"(d) : "l"(a), "l"(b));
}
__device__ __forceinline__ float sigf(float x) {
    float e = __expf(-x);
    return __fdividef(1.0f, 1.0f + e);
}
// pack two fp32 -> f16x2 (lo = x, hi = y)
__device__ __forceinline__ unsigned packh2(float x, float y) {
    unsigned r;
    asm("cvt.rn.f16x2.f32 %0, %2, %1;" : "=r"(r) : "f"(x), "f"(y));
    return r;
}
// unpack f16x2 -> two fp32
__device__ __forceinline__ float2 unpackh2(unsigned v) {
    float2 r;
    unsigned short lo = (unsigned short)(v & 0xFFFFu);
    unsigned short hi = (unsigned short)(v >> 16);
    asm("cvt.f32.f16 %0, %1;" : "=f"(r.x) : "h"(lo));
    asm("cvt.f32.f16 %0, %1;" : "=f"(r.y) : "h"(hi));
    return r;
}

// swizzled transposed x tile: float4 block (k, rb) at k*16 + (rb ^ (k&15))
__device__ __forceinline__ void fill_x(float* xsf, const float* __restrict__ inp,
                                       int t0, int tid) {
    #pragma unroll
    for (int p = 0; p < 4; p++) {
        int i = tid + p * 256;
        int r = i >> 4, c = i & 15;
        float4 v = *(const float4*)(inp + (size_t)(t0 + r) * 64 + 4 * c);
        int rb = r >> 2, r3 = r & 3;
        #pragma unroll
        for (int j = 0; j < 4; j++) {
            int k = 4 * c + j;
            float val = (j == 0) ? v.x : (j == 1) ? v.y : (j == 2) ? v.z : v.w;
            xsf[(k * 16 + (rb ^ (k & 15))) * 4 + r3] = val;
        }
    }
}

// GEMM1 core: 8 rows (4 packed pairs) x 4 channels per thread
__device__ __forceinline__ void gemm1_core(const float4* xs4, const float4* w4,
                                           int ri, int ci,
                                           u64 aL0[4], u64 aL1[4],
                                           u64 aR0[4], u64 aR1[4]) {
    const int rb0 = 2 * ri, rb1 = 2 * ri + 1;
    #pragma unroll
    for (int q = 0; q < 4; q++) { aL0[q]=0ull; aL1[q]=0ull; aR0[q]=0ull; aR1[q]=0ull; }
    #pragma unroll 1
    for (int k0 = 0; k0 < 64; k0 += 16) {
        #pragma unroll
        for (int j = 0; j < 16; j++) {
            const int k = k0 + j;
            ulonglong2 xA = *(const ulonglong2*)(xs4 + k * 16 + (rb0 ^ j));
            ulonglong2 xB = *(const ulonglong2*)(xs4 + k * 16 + (rb1 ^ j));
            float4 wv = w4[k * 32 + ci];
            u64 wl0 = pk2(wv.x, wv.x), wl1 = pk2(wv.y, wv.y);
            u64 wr0 = pk2(wv.z, wv.z), wr1 = pk2(wv.w, wv.w);
            ffma2(aL0[0], xA.x, wl0); ffma2(aL0[1], xA.y, wl0);
            ffma2(aL0[2], xB.x, wl0); ffma2(aL0[3], xB.y, wl0);
            ffma2(aL1[0], xA.x, wl1); ffma2(aL1[1], xA.y, wl1);
            ffma2(aL1[2], xB.x, wl1); ffma2(aL1[3], xB.y, wl1);
            ffma2(aR0[0], xA.x, wr0); ffma2(aR0[1], xA.y, wr0);
            ffma2(aR0[2], xB.x, wr0); ffma2(aR0[3], xB.y, wr0);
            ffma2(aR1[0], xA.x, wr1); ffma2(aR1[1], xA.y, wr1);
            ffma2(aR1[2], xB.x, wr1); ffma2(aR1[3], xB.y, wr1);
        }
    }
}

__device__ __forceinline__ void build_w1i(float4* W1i4, const float* __restrict__ W1, int tid) {
    #pragma unroll
    for (int p = 0; p < 8; p++) {
        int idx = tid + p * 256;
        int k = idx >> 5, cc = idx & 31;
        float2 l = *(const float2*)(W1 + k * 128 + 2 * cc);
        float2 r = *(const float2*)(W1 + k * 128 + 64 + 2 * cc);
        W1i4[idx] = make_float4(l.x, l.y, r.x, r.y);
    }
}

// ============================================================================
// k1: GEMM1 + gate -> g_ab (fp16 packed) + per-64-row-chunk aggregates (fp32)
// ============================================================================
__global__ __launch_bounds__(256, 3)
void k1_gemm1(const float* __restrict__ inp,
              const float* __restrict__ W1,
              const float* __restrict__ B1) {
    extern __shared__ float sm[];
    float4* W1i4  = (float4*)sm;                 // [0,32768)
    float*  xsf   = sm + 8192;                   // [32768,49152)
    float2* parts = (float2*)(sm + 12288);       // [49152,53248)

    const int tid = threadIdx.x, c = blockIdx.x;
    const int ri = tid >> 5, ci = tid & 31;

    build_w1i(W1i4, W1, tid);
    const float bl0 = B1[2 * ci],      bl1 = B1[2 * ci + 1];
    const float br0 = B1[64 + 2 * ci], br1 = B1[64 + 2 * ci + 1];
    __syncthreads();

    #pragma unroll 1
    for (int tt = 0; tt < 2; tt++) {
        const int chunk = 2 * c + tt;
        const int t0 = chunk * TILE_R;
        fill_x(xsf, inp, t0, tid);
        __syncthreads();

        u64 aL0[4], aL1[4], aR0[4], aR1[4];
        gemm1_core((const float4*)xsf, W1i4, ri, ci, aL0, aL1, aR0, aR1);

        float A0 = 1.f, B0 = 0.f, A1 = 1.f, B1v = 0.f;
        #pragma unroll
        for (int p2 = 0; p2 < 4; p2++) {
            float2 L0 = upk(aL0[p2]), L1 = upk(aL1[p2]);
            float2 R0 = upk(aR0[p2]), R1 = upk(aR1[p2]);
            #pragma unroll
            for (int e = 0; e < 2; e++) {
                int r = 8 * ri + 2 * p2 + e;
                float l0 = sigf((e ? L0.y : L0.x) + bl0);
                float l1 = sigf((e ? L1.y : L1.x) + bl1);
                float r0 = sigf((e ? R0.y : R0.x) + br0);
                float r1 = sigf((e ? R1.y : R1.x) + br1);
                float a0 = l0 * r0, b0 = 1.f - l0;
                float a1 = l1 * r1, b1 = 1.f - l1;
                g_ab[(size_t)(t0 + r) * 32 + ci] =
                    make_uint2(packh2(a0, a1), packh2(b0, b1));
                B0  = fmaf(a0, B0, b0);  A0 *= a0;
                B1v = fmaf(a1, B1v, b1); A1 *= a1;
            }
        }
        ((float4*)parts)[ri * 32 + ci] = make_float4(A0, B0, A1, B1v);
        __syncthreads();

        if (tid < 64) {
            float Ac = 1.f, Bc = 0.f;
            #pragma unroll
            for (int g = 0; g < 8; g++) {
                float2 pp = parts[g * 64 + tid];
                Bc = fmaf(pp.x, Bc, pp.y);
                Ac *= pp.x;
            }
            g_Ac[chunk * 64 + tid] = Ac;
            g_Bc[chunk * 64 + tid] = Bc;
        }
        __syncthreads();
    }
}

// ============================================================================
// k2a: super aggregates — 4 segments x 64 channels per CTA, prefetched
// ============================================================================
__global__ __launch_bounds__(256, 8)
void k2a_super_agg() {
    __shared__ float2 parts[4 * 64];
    const int s = blockIdx.x;
    const int j = threadIdx.x & 63, seg = threadIdx.x >> 6;
    const int base = s * SUPER + seg * SEGC;

    float A = 1.f, B = 0.f;
    #pragma unroll 1
    for (int bq = 0; bq < SEGC / 8; bq++) {
        float a_[8], b_[8];
        #pragma unroll
        for (int i = 0; i < 8; i++) {
            a_[i] = g_Ac[(base + bq * 8 + i) * 64 + j];
            b_[i] = g_Bc[(base + bq * 8 + i) * 64 + j];
        }
        #pragma unroll
        for (int i = 0; i < 8; i++) { B = fmaf(a_[i], B, b_[i]); A *= a_[i]; }
    }
    parts[seg * 64 + j] = make_float2(A, B);
    __syncthreads();

    if (threadIdx.x < 64) {
        float As = 1.f, Bs = 0.f;
        #pragma unroll
        for (int g = 0; g < 4; g++) {
            float2 pp = parts[g * 64 + threadIdx.x];
            Bs = fmaf(pp.x, Bs, pp.y);
            As *= pp.x;
        }
        g_A2[s * 64 + threadIdx.x] = As;
        g_B2[s * 64 + threadIdx.x] = Bs;
    }
}

// ============================================================================
// k2b: scan over 64 supers, prefetched in batches of 16
// ============================================================================
__global__ void k2b_super_scan() {
    const int j = threadIdx.x;
    float u = 0.f;
    #pragma unroll 1
    for (int bq = 0; bq < NSUPER / 16; bq++) {
        float A_[16], B_[16];
        #pragma unroll
        for (int i = 0; i < 16; i++) {
            A_[i] = g_A2[(bq * 16 + i) * 64 + j];
            B_[i] = g_B2[(bq * 16 + i) * 64 + j];
        }
        #pragma unroll
        for (int i = 0; i < 16; i++) {
            g_U2[(bq * 16 + i) * 64 + j] = u;
            u = fmaf(A_[i], u, B_[i]);
        }
    }
}

// ============================================================================
// k2c: expand to chunk-start states — segmented + prefetched
// ============================================================================
__global__ __launch_bounds__(256, 8)
void k2c_expand() {
    __shared__ float2 parts[4 * 64];
    __shared__ float  segu [4 * 64];
    const int s = blockIdx.x;
    const int j = threadIdx.x & 63, seg = threadIdx.x >> 6;
    const int base = s * SUPER + seg * SEGC;

    float A = 1.f, B = 0.f;
    #pragma unroll 1
    for (int bq = 0; bq < SEGC / 8; bq++) {
        float a_[8], b_[8];
        #pragma unroll
        for (int i = 0; i < 8; i++) {
            a_[i] = g_Ac[(base + bq * 8 + i) * 64 + j];
            b_[i] = g_Bc[(base + bq * 8 + i) * 64 + j];
        }
        #pragma unroll
        for (int i = 0; i < 8; i++) { B = fmaf(a_[i], B, b_[i]); A *= a_[i]; }
    }
    parts[seg * 64 + j] = make_float2(A, B);
    __syncthreads();

    if (threadIdx.x < 64) {
        float u = g_U2[s * 64 + threadIdx.x];
        #pragma unroll
        for (int g = 0; g < 4; g++) {
            segu[g * 64 + threadIdx.x] = u;
            float2 pp = parts[g * 64 + threadIdx.x];
            u = fmaf(pp.x, u, pp.y);
        }
    }
    __syncthreads();

    float u = segu[seg * 64 + j];
    #pragma unroll 1
    for (int bq = 0; bq < SEGC / 8; bq++) {
        float a_[8], b_[8];
        #pragma unroll
        for (int i = 0; i < 8; i++) {
            a_[i] = g_Ac[(base + bq * 8 + i) * 64 + j];
            b_[i] = g_Bc[(base + bq * 8 + i) * 64 + j];
        }
        #pragma unroll
        for (int i = 0; i < 8; i++) {
            g_U[(base + bq * 8 + i) * 64 + j] = u;
            u = fmaf(a_[i], u, b_[i]);
        }
    }
}

// ============================================================================
// k3: load fp16 a,b -> parallel replay -> swizzled z tile -> GEMM2 -> out
// ============================================================================
__global__ __launch_bounds__(256, 4)
void k3_replay_gemm2(const float* __restrict__ W2,
                     const float* __restrict__ B2,
                     float* __restrict__ out) {
    extern __shared__ float sm[];
    float*  zsf   = sm;                          // [0,16384)
    float2* parts = (float2*)(sm + 4096);        // [16384,20480)
    float*  ust   = sm + 5120;                   // [20480,22528)
    u64*    W2d   = (u64*)(sm + 5632);           // [22528,38912)

    const int tid = threadIdx.x, c = blockIdx.x;
    const int ri = tid >> 5, ci = tid & 31;
    const int oc = tid & 31, rp = tid >> 5;
    const int t0 = c * TILE_R;

    #pragma unroll
    for (int p = 0; p < 8; p++) {
        int idx = tid + p * 256;
        float w = W2[idx];
        W2d[idx] = pk2(w, w);
    }
    const float b2 = B2[oc];
    if (c == 0 && tid < 32) out[tid] = B2[tid];

    // load packed fp16 a,b for this thread's 8 rows x channel pair
    float4 ab[8];
    #pragma unroll
    for (int e = 0; e < 8; e++) {
        uint2 v = g_ab[(size_t)(t0 + 8 * ri + e) * 32 + ci];
        float2 aa = unpackh2(v.x);
        float2 bb = unpackh2(v.y);
        ab[e] = make_float4(aa.x, aa.y, bb.x, bb.y);
    }

    float A0 = 1.f, B0 = 0.f, A1 = 1.f, B1v = 0.f;
    #pragma unroll
    for (int e = 0; e < 8; e++) {
        B0  = fmaf(ab[e].x, B0,  ab[e].z);  A0 *= ab[e].x;
        B1v = fmaf(ab[e].y, B1v, ab[e].w);  A1 *= ab[e].y;
    }
    ((float4*)parts)[ri * 32 + ci] = make_float4(A0, B0, A1, B1v);
    __syncthreads();

    if (tid < 64) {
        float u = g_U[c * 64 + tid];
        #pragma unroll
        for (int g = 0; g < 8; g++) {
            ust[g * 64 + tid] = u;
            float2 pp = parts[g * 64 + tid];
            u = fmaf(pp.x, u, pp.y);
        }
    }
    __syncthreads();

    {
        float2 us = *(const float2*)(ust + ri * 64 + 2 * ci);
        float u0 = us.x, u1 = us.y;
        const int j0 = 2 * ci, j1 = 2 * ci + 1;
        #pragma unroll
        for (int e = 0; e < 8; e++) {
            u0 = fmaf(ab[e].x, u0, ab[e].z);
            u1 = fmaf(ab[e].y, u1, ab[e].w);
            int r = 8 * ri + e;
            zsf[(j0 * 16 + ((r >> 2) ^ (j0 & 15))) * 4 + (r & 3)] = u0;
            zsf[(j1 * 16 + ((r >> 2) ^ (j1 & 15))) * 4 + (r & 3)] = u1;
        }
    }
    __syncthreads();

    u64 acc0 = pk2(b2, b2), acc1 = acc0, acc2 = acc0, acc3 = acc0;
    {
        const int rb0 = 2 * rp, rb1 = 2 * rp + 1;
        const float4* zs4 = (const float4*)zsf;
        #pragma unroll 1
        for (int k0 = 0; k0 < 64; k0 += 16) {
            #pragma unroll
            for (int j = 0; j < 16; j++) {
                const int k = k0 + j;
                ulonglong2 zA = *(const ulonglong2*)(zs4 + k * 16 + (rb0 ^ j));
                ulonglong2 zB = *(const ulonglong2*)(zs4 + k * 16 + (rb1 ^ j));
                u64 wd = W2d[k * 32 + oc];
                ffma2(acc0, zA.x, wd); ffma2(acc1, zA.y, wd);
                ffma2(acc2, zB.x, wd); ffma2(acc3, zB.y, wd);
            }
        }
    }
    #pragma unroll
    for (int q = 0; q < 4; q++) {
        u64 a = (q == 0) ? acc0 : (q == 1) ? acc1 : (q == 2) ? acc2 : acc3;
        float2 v = upk(a);
        int t = t0 + 1 + 8 * rp + 2 * q;
        if (t < T_TOTAL)     out[(size_t)t * 32 + oc]       = v.x;
        if (t + 1 < T_TOTAL) out[(size_t)(t + 1) * 32 + oc] = v.y;
    }
}

// ============================================================================
// launch
// ============================================================================
extern "C" void kernel_launch(void* const* d_in, const int* in_sizes, int n_in,
                              void* d_out, int out_size) {
    const float* inp = (const float*)d_in[0];
    const float* W1  = (const float*)d_in[1];
    const float* B1  = (const float*)d_in[2];
    const float* W2  = (const float*)d_in[3];
    const float* B2  = (const float*)d_in[4];
    float* out = (float*)d_out;

    const int smem1 = 53248;
    const int smem3 = 38912;
    cudaFuncSetAttribute(k1_gemm1,        cudaFuncAttributeMaxDynamicSharedMemorySize, smem1);
    cudaFuncSetAttribute(k3_replay_gemm2, cudaFuncAttributeMaxDynamicSharedMemorySize, smem3);

    k1_gemm1<<<K1_BLK, 256, smem1>>>(inp, W1, B1);
    k2a_super_agg<<<NSUPER, 256>>>();
    k2b_super_scan<<<1, 64>>>();
    k2c_expand<<<NSUPER, 256>>>();
    k3_replay_gemm2<<<NCHUNK, 256, smem3>>>(W2, B2, out);
    (void)in_sizes; (void)n_in; (void)out_size;
}